// round 10
// baseline (speedup 1.0000x reference)
#include <cuda_runtime.h>
#include <cuda_bf16.h>
#include <cstdint>
#include <math.h>

// Problem constants
#define B_  64
#define T_  1024
#define I_  128
#define H_  256
#define NT  (B_ * T_)          // 65536 rows

typedef unsigned long long u64;

// ---------------------------------------------------------------------------
// Static device scratch (no runtime allocation allowed)
// ---------------------------------------------------------------------------
__device__ float2 g_Z[(size_t)NT * H_];        // {zf, zc} x-part (+bias), 128 MB
__device__ float  g_y1[(size_t)NT * H_];       // layer-1 outputs, 64 MB
__device__ u64    g_Wh[2][H_ * H_];            // recurrent weights {wf,wc} packed, k-major

// ---------------------------------------------------------------------------
// f32x2 + PTX helpers
// ---------------------------------------------------------------------------
__device__ __forceinline__ u64 pack2(float x, float y) {
    u64 r;
    asm("mov.b64 %0, {%1, %2};" : "=l"(r) : "f"(x), "f"(y));
    return r;
}
__device__ __forceinline__ void unpack2(u64 v, float& x, float& y) {
    asm("mov.b64 {%0, %1}, %2;" : "=f"(x), "=f"(y) : "l"(v));
}
__device__ __forceinline__ void ffma2(u64& d, u64 a, u64 b) {
    asm("fma.rn.f32x2 %0, %1, %2, %0;" : "+l"(d) : "l"(a), "l"(b));
}
__device__ __forceinline__ u64 fadd2(u64 a, u64 b) {
    u64 d;
    asm("add.rn.f32x2 %0, %1, %2;" : "=l"(d) : "l"(a), "l"(b));
    return d;
}
__device__ __forceinline__ float tanh_fast(float x) {   // MUFU.TANH
    float y;
    asm("tanh.approx.f32 %0, %1;" : "=f"(y) : "f"(x));
    return y;
}
__device__ __forceinline__ uint32_t smem_u32(const void* p) {
    uint32_t a;
    asm("{ .reg .u64 t; cvta.to.shared.u64 t, %1; cvt.u32.u64 %0, t; }"
        : "=r"(a) : "l"(p));
    return a;
}
__device__ __forceinline__ uint32_t cluster_rank() {
    uint32_t r;
    asm("mov.u32 %0, %%cluster_ctarank;" : "=r"(r));
    return r;
}
__device__ __forceinline__ uint32_t mapa_u32(uint32_t addr, uint32_t rank) {
    uint32_t r;
    asm("mapa.shared::cluster.u32 %0, %1, %2;" : "=r"(r) : "r"(addr), "r"(rank));
    return r;
}
__device__ __forceinline__ void st_cluster_u64(uint32_t addr, u64 v) {
    asm volatile("st.shared::cluster.u64 [%0], %1;" :: "r"(addr), "l"(v) : "memory");
}
__device__ __forceinline__ void cluster_arrive() {
    asm volatile("barrier.cluster.arrive.aligned;" ::: "memory");
}
__device__ __forceinline__ void cluster_wait() {
    asm volatile("barrier.cluster.wait.aligned;" ::: "memory");
}

// ---------------------------------------------------------------------------
// Repack recurrent weight rows: g_Wh[layer][k*H + j] = pack{Wf[D+k][j], Wc[D+k][j]}
// ---------------------------------------------------------------------------
__global__ void repack_wh(const float* __restrict__ Wf, const float* __restrict__ Wc,
                          int D, int layer)
{
    int j = threadIdx.x;
    int k = blockIdx.x;
    float wf = Wf[(size_t)(D + k) * H_ + j];
    float wc = Wc[(size_t)(D + k) * H_ + j];
    g_Wh[layer][k * H_ + j] = pack2(wf, wc);
}

// ---------------------------------------------------------------------------
// Precompute x-part of both gates (unchanged, passing since round 6):
//   g_Z[n][j] = { bf[j] + sum_d X[n][d]*Wf[d][j],  bc[j] + sum_d X[n][d]*Wc[d][j] }
// ---------------------------------------------------------------------------
__global__ void __launch_bounds__(256) gemm_x(
    const float* __restrict__ Xext, int D, int useY1,
    const float* __restrict__ Wf, const float* __restrict__ Wc,
    const float* __restrict__ bf, const float* __restrict__ bc)
{
    const float* __restrict__ X = useY1 ? (const float*)g_y1 : Xext;

    __shared__ float2 Xs[16][130];   // x splatted {x,x}
    __shared__ float2 Ws[16][34];    // {wf,wc}

    const int tid = threadIdx.x;
    const int tx  = tid & 15;
    const int ty  = tid >> 4;
    const int n0  = blockIdx.x * 128;
    const int j0  = blockIdx.y * 32;
    const int jj  = j0 + 2 * tx;

    u64 acc[8][2];
    {
        u64 bi0 = pack2(bf[jj],     bc[jj]);
        u64 bi1 = pack2(bf[jj + 1], bc[jj + 1]);
#pragma unroll
        for (int r = 0; r < 8; r++) { acc[r][0] = bi0; acc[r][1] = bi1; }
    }

    for (int d0 = 0; d0 < D; d0 += 16) {
        __syncthreads();
        {
            int r  = tid >> 2;
            int c4 = (tid & 3) * 4;
#pragma unroll
            for (int rr = 0; rr < 2; rr++) {
                int row = r + rr * 64;
                float4 v = *(const float4*)&X[(size_t)(n0 + row) * D + d0 + c4];
                Xs[c4 + 0][row] = make_float2(v.x, v.x);
                Xs[c4 + 1][row] = make_float2(v.y, v.y);
                Xs[c4 + 2][row] = make_float2(v.z, v.z);
                Xs[c4 + 3][row] = make_float2(v.w, v.w);
            }
        }
        for (int e = tid; e < 512; e += 256) {
            int k = e >> 5, jw = e & 31;
            Ws[k][jw] = make_float2(Wf[(size_t)(d0 + k) * H_ + j0 + jw],
                                    Wc[(size_t)(d0 + k) * H_ + j0 + jw]);
        }
        __syncthreads();

#pragma unroll
        for (int kk = 0; kk < 16; kk++) {
            ulonglong2 wq = *(const ulonglong2*)&Ws[kk][2 * tx];
            const ulonglong2* xp = (const ulonglong2*)&Xs[kk][ty * 8];
#pragma unroll
            for (int q = 0; q < 4; q++) {
                ulonglong2 xq = xp[q];
                ffma2(acc[2 * q + 0][0], xq.x, wq.x);
                ffma2(acc[2 * q + 0][1], xq.x, wq.y);
                ffma2(acc[2 * q + 1][0], xq.y, wq.x);
                ffma2(acc[2 * q + 1][1], xq.y, wq.y);
            }
        }
    }

#pragma unroll
    for (int r = 0; r < 8; r++) {
        int n = n0 + ty * 8 + r;
        float4 v;
        unpack2(acc[r][0], v.x, v.y);
        unpack2(acc[r][1], v.z, v.w);
        *(float4*)&g_Z[(size_t)n * H_ + jj] = v;
    }
}

// ---------------------------------------------------------------------------
// Recurrence v4: cluster of 4 CTAs, CTA = 64 columns x full K, 2 batches.
// 512 threads (16 warps): thread = (col jl, K-eighth kq), 16 k-pairs in regs
// (64 regs of weights). Parallel epilogue: 128 task threads, one (col,batch)
// each, MUFU.TANH for both gates. h exchanged via DSMEM into parity
// double-buffered arrays; split cluster barrier overlapped with Y/z traffic.
// ---------------------------------------------------------------------------
__global__ void __cluster_dims__(4, 1, 1) __launch_bounds__(512, 1)
mgu_recur4(int layer, float* __restrict__ Yext, float* __restrict__ Hfin)
{
    __shared__ __align__(16) u64 hbuf[2][2][256];   // [parity][batch][k] splatted {h,h}
    __shared__ __align__(16) u64 red[2][8][65];     // [batch][kq][col] partial sums

    const int tid = threadIdx.x;
    const int jl  = tid & 63;              // local column
    const int kq  = tid >> 6;              // K-eighth 0..7
    const uint32_t rank = cluster_rank();  // 0..3 -> column block
    const int c   = blockIdx.x >> 2;       // cluster id -> batch pair
    const int b0  = 2 * c, b1 = 2 * c + 1;
    const int jg  = (int)rank * 64 + jl;   // global column

    const u64* __restrict__ Whg = g_Wh[layer];
    float* __restrict__ Y = (layer == 0) ? (float*)g_y1 : Yext;

    // This thread's 16 weight k-pairs -> registers (step-invariant).
    u64 wreg[32];
#pragma unroll
    for (int i = 0; i < 16; i++) {
        int k = 2 * (kq * 16 + i);
        wreg[2 * i]     = Whg[(size_t)k * H_ + jg];
        wreg[2 * i + 1] = Whg[(size_t)(k + 1) * H_ + jg];
    }

    // zero parity-0 h buffers (parity-1 is written by peers at step 0)
    (&hbuf[0][0][0])[tid] = 0ULL;
    __syncthreads();
    cluster_arrive();   // no peer may start step 0 before all init done
    cluster_wait();

    const uint32_t hb_addr = smem_u32(&hbuf[0][0][0]);
    uint32_t peer[4];
#pragma unroll
    for (int r = 0; r < 4; r++) peer[r] = mapa_u32(hb_addr, (uint32_t)r);

    // Epilogue task mapping: tid < 128 -> (batch bsel, column tcol)
    const int  bsel   = tid >> 6;                       // 0/1 (valid for tid<128)
    const int  tcol   = jl;                             // 0..63
    const int  tjg    = (int)rank * 64 + tcol;
    const bool isTask = (tid < 128);
    const size_t zbT  = (size_t)(b0 + bsel) * T_ * H_ + tjg;  // task z/Y index base

    float2 zt = make_float2(0.f, 0.f);
    if (isTask) zt = g_Z[zbT];             // prefetch z for t=0

    for (int t = 0; t < T_; t++) {
        const int p = t & 1, q = p ^ 1;
        const u64* __restrict__ hbp0 = &hbuf[p][0][0];
        const u64* __restrict__ hbp1 = &hbuf[p][1][0];

        u64 a0e = 0, a0o = 0, a1e = 0, a1o = 0;
#pragma unroll
        for (int i = 0; i < 16; i++) {
            int kp = kq * 16 + i;
            ulonglong2 ha = *(const ulonglong2*)(hbp0 + 2 * kp);  // broadcast
            ulonglong2 hb = *(const ulonglong2*)(hbp1 + 2 * kp);  // broadcast
            ffma2(a0e, ha.x, wreg[2 * i]);
            ffma2(a0o, ha.y, wreg[2 * i + 1]);
            ffma2(a1e, hb.x, wreg[2 * i]);
            ffma2(a1o, hb.y, wreg[2 * i + 1]);
        }
        red[0][kq][jl] = fadd2(a0e, a0o);
        red[1][kq][jl] = fadd2(a1e, a1o);
        __syncthreads();

        float hn = 0.f;
        if (isTask) {
            u64 s = fadd2(fadd2(fadd2(red[bsel][0][tcol], red[bsel][1][tcol]),
                                fadd2(red[bsel][2][tcol], red[bsel][3][tcol])),
                          fadd2(fadd2(red[bsel][4][tcol], red[bsel][5][tcol]),
                                fadd2(red[bsel][6][tcol], red[bsel][7][tcol])));
            float af, ac;
            unpack2(s, af, ac);
            af += zt.x;
            ac += zt.y;

            float hold, dm;
            unpack2((bsel ? hbp1 : hbp0)[tjg], hold, dm);
            (void)dm;

            float f  = fmaf(0.5f, tanh_fast(0.5f * af), 0.5f);   // sigmoid
            float cg = tanh_fast(ac);
            hn = fmaf(f, hold - cg, cg);                         // f*h + (1-f)*c

            u64 pk = pack2(hn, hn);
            uint32_t off = (uint32_t)(((q * 2 + bsel) * 256 + tjg) * 8);
#pragma unroll
            for (int r = 0; r < 4; r++)
                st_cluster_u64(peer[r] + off, pk);   // includes self
        }
        cluster_arrive();   // release: DSMEM h stores ordered cluster-wide

        // overlap the barrier with global traffic
        if (isTask) {
            Y[zbT + (size_t)t * H_] = hn;
            if (t == T_ - 1) {
                Hfin[(b0 + bsel) * H_ + tjg] = hn;
            } else {
                zt = g_Z[zbT + (size_t)(t + 1) * H_];
            }
        }
        cluster_wait();     // acquire: peers' h for parity q now visible
    }
}

// ---------------------------------------------------------------------------
// Launch
// ---------------------------------------------------------------------------
extern "C" void kernel_launch(void* const* d_in, const int* in_sizes, int n_in,
                              void* d_out, int out_size)
{
    const float* x   = (const float*)d_in[0];
    const float* Wf1 = (const float*)d_in[1];
    const float* bf1 = (const float*)d_in[2];
    const float* Wc1 = (const float*)d_in[3];
    const float* bc1 = (const float*)d_in[4];
    const float* Wf2 = (const float*)d_in[5];
    const float* bf2 = (const float*)d_in[6];
    const float* Wc2 = (const float*)d_in[7];
    const float* bc2 = (const float*)d_in[8];

    float* out = (float*)d_out;
    float* y2  = out;                               // [B, T, H]
    float* h1  = out + (size_t)NT * H_;             // hidden[0]
    float* h2  = h1 + (size_t)B_ * H_;              // hidden[1]

    // weight repack (both layers)
    repack_wh<<<H_, H_>>>(Wf1, Wc1, I_, 0);
    repack_wh<<<H_, H_>>>(Wf2, Wc2, H_, 1);

    // layer 1
    gemm_x<<<dim3(NT / 128, H_ / 32), 256>>>(x, I_, 0, Wf1, Wc1, bf1, bc1);
    mgu_recur4<<<128, 512>>>(0, nullptr, h1);

    // layer 2 (reads g_y1)
    gemm_x<<<dim3(NT / 128, H_ / 32), 256>>>(nullptr, H_, 1, Wf2, Wc2, bf2, bc2);
    mgu_recur4<<<128, 512>>>(1, y2, h2);
}

// round 12
// speedup vs baseline: 1.3766x; 1.3766x over previous
#include <cuda_runtime.h>
#include <cuda_bf16.h>
#include <cstdint>
#include <math.h>

// Problem constants
#define B_  64
#define T_  1024
#define I_  128
#define H_  256
#define NT  (B_ * T_)          // 65536 rows

typedef unsigned long long u64;

// ---------------------------------------------------------------------------
// Static device scratch (no runtime allocation allowed)
// ---------------------------------------------------------------------------
__device__ float2 g_Z[(size_t)NT * H_];        // {zf, zc} x-part (+bias), 128 MB
__device__ float  g_y1[(size_t)NT * H_];       // layer-1 outputs, 64 MB
__device__ u64    g_Wh[2][H_ * H_];            // recurrent weights {wf,wc} packed, k-major

// ---------------------------------------------------------------------------
// f32x2 + PTX helpers
// ---------------------------------------------------------------------------
__device__ __forceinline__ u64 pack2(float x, float y) {
    u64 r;
    asm("mov.b64 %0, {%1, %2};" : "=l"(r) : "f"(x), "f"(y));
    return r;
}
__device__ __forceinline__ void unpack2(u64 v, float& x, float& y) {
    asm("mov.b64 {%0, %1}, %2;" : "=f"(x), "=f"(y) : "l"(v));
}
__device__ __forceinline__ void ffma2(u64& d, u64 a, u64 b) {
    asm("fma.rn.f32x2 %0, %1, %2, %0;" : "+l"(d) : "l"(a), "l"(b));
}
__device__ __forceinline__ u64 fadd2(u64 a, u64 b) {
    u64 d;
    asm("add.rn.f32x2 %0, %1, %2;" : "=l"(d) : "l"(a), "l"(b));
    return d;
}
__device__ __forceinline__ float tanh_fast(float x) {   // MUFU.TANH
    float y;
    asm("tanh.approx.f32 %0, %1;" : "=f"(y) : "f"(x));
    return y;
}
__device__ __forceinline__ uint32_t smem_u32(const void* p) {
    uint32_t a;
    asm("{ .reg .u64 t; cvta.to.shared.u64 t, %1; cvt.u32.u64 %0, t; }"
        : "=r"(a) : "l"(p));
    return a;
}
__device__ __forceinline__ uint32_t cluster_rank() {
    uint32_t r;
    asm("mov.u32 %0, %%cluster_ctarank;" : "=r"(r));
    return r;
}
__device__ __forceinline__ uint32_t mapa_u32(uint32_t addr, uint32_t rank) {
    uint32_t r;
    asm("mapa.shared::cluster.u32 %0, %1, %2;" : "=r"(r) : "r"(addr), "r"(rank));
    return r;
}
__device__ __forceinline__ void st_cluster_u64(uint32_t addr, u64 v) {
    asm volatile("st.shared::cluster.u64 [%0], %1;" :: "r"(addr), "l"(v) : "memory");
}
__device__ __forceinline__ void cluster_arrive() {
    asm volatile("barrier.cluster.arrive.aligned;" ::: "memory");
}
__device__ __forceinline__ void cluster_wait() {
    asm volatile("barrier.cluster.wait.aligned;" ::: "memory");
}
__device__ __forceinline__ void mbar_init(uint32_t addr, uint32_t count) {
    asm volatile("mbarrier.init.shared.b64 [%0], %1;" :: "r"(addr), "r"(count) : "memory");
}
__device__ __forceinline__ void fence_cluster() {
    asm volatile("fence.acq_rel.cluster;" ::: "memory");
}
__device__ __forceinline__ void mbar_arrive_cluster(uint32_t remote_addr) {
    asm volatile("mbarrier.arrive.shared::cluster.b64 _, [%0];"
                 :: "r"(remote_addr) : "memory");
}
// Spin-wait on local mbarrier phase, cluster-scope acquire.
__device__ __forceinline__ void mbar_wait_cluster(uint32_t addr, uint32_t parity) {
    uint32_t done;
    asm volatile(
        "{\n\t"
        ".reg .pred p;\n\t"
        "mbarrier.try_wait.parity.acquire.cluster.shared::cta.b64 p, [%1], %2;\n\t"
        "selp.b32 %0, 1, 0, p;\n\t"
        "}"
        : "=r"(done) : "r"(addr), "r"(parity) : "memory");
    if (!done) {
        asm volatile(
            "{\n\t"
            ".reg .pred P1;\n\t"
            "WAIT_LOOP_%=:\n\t"
            "mbarrier.try_wait.parity.acquire.cluster.shared::cta.b64 P1, [%0], %1, 0x989680;\n\t"
            "@P1 bra.uni WAIT_DONE_%=;\n\t"
            "bra.uni WAIT_LOOP_%=;\n\t"
            "WAIT_DONE_%=:\n\t"
            "}"
            :: "r"(addr), "r"(parity) : "memory");
    }
}

// ---------------------------------------------------------------------------
// Repack recurrent weight rows: g_Wh[layer][k*H + j] = pack{Wf[D+k][j], Wc[D+k][j]}
// ---------------------------------------------------------------------------
__global__ void repack_wh(const float* __restrict__ Wf, const float* __restrict__ Wc,
                          int D, int layer)
{
    int j = threadIdx.x;
    int k = blockIdx.x;
    float wf = Wf[(size_t)(D + k) * H_ + j];
    float wc = Wc[(size_t)(D + k) * H_ + j];
    g_Wh[layer][k * H_ + j] = pack2(wf, wc);
}

// ---------------------------------------------------------------------------
// Precompute x-part of both gates (unchanged, passing since round 6):
//   g_Z[n][j] = { bf[j] + sum_d X[n][d]*Wf[d][j],  bc[j] + sum_d X[n][d]*Wc[d][j] }
// ---------------------------------------------------------------------------
__global__ void __launch_bounds__(256) gemm_x(
    const float* __restrict__ Xext, int D, int useY1,
    const float* __restrict__ Wf, const float* __restrict__ Wc,
    const float* __restrict__ bf, const float* __restrict__ bc)
{
    const float* __restrict__ X = useY1 ? (const float*)g_y1 : Xext;

    __shared__ float2 Xs[16][130];   // x splatted {x,x}
    __shared__ float2 Ws[16][34];    // {wf,wc}

    const int tid = threadIdx.x;
    const int tx  = tid & 15;
    const int ty  = tid >> 4;
    const int n0  = blockIdx.x * 128;
    const int j0  = blockIdx.y * 32;
    const int jj  = j0 + 2 * tx;

    u64 acc[8][2];
    {
        u64 bi0 = pack2(bf[jj],     bc[jj]);
        u64 bi1 = pack2(bf[jj + 1], bc[jj + 1]);
#pragma unroll
        for (int r = 0; r < 8; r++) { acc[r][0] = bi0; acc[r][1] = bi1; }
    }

    for (int d0 = 0; d0 < D; d0 += 16) {
        __syncthreads();
        {
            int r  = tid >> 2;
            int c4 = (tid & 3) * 4;
#pragma unroll
            for (int rr = 0; rr < 2; rr++) {
                int row = r + rr * 64;
                float4 v = *(const float4*)&X[(size_t)(n0 + row) * D + d0 + c4];
                Xs[c4 + 0][row] = make_float2(v.x, v.x);
                Xs[c4 + 1][row] = make_float2(v.y, v.y);
                Xs[c4 + 2][row] = make_float2(v.z, v.z);
                Xs[c4 + 3][row] = make_float2(v.w, v.w);
            }
        }
        for (int e = tid; e < 512; e += 256) {
            int k = e >> 5, jw = e & 31;
            Ws[k][jw] = make_float2(Wf[(size_t)(d0 + k) * H_ + j0 + jw],
                                    Wc[(size_t)(d0 + k) * H_ + j0 + jw]);
        }
        __syncthreads();

#pragma unroll
        for (int kk = 0; kk < 16; kk++) {
            ulonglong2 wq = *(const ulonglong2*)&Ws[kk][2 * tx];
            const ulonglong2* xp = (const ulonglong2*)&Xs[kk][ty * 8];
#pragma unroll
            for (int q = 0; q < 4; q++) {
                ulonglong2 xq = xp[q];
                ffma2(acc[2 * q + 0][0], xq.x, wq.x);
                ffma2(acc[2 * q + 0][1], xq.x, wq.y);
                ffma2(acc[2 * q + 1][0], xq.y, wq.x);
                ffma2(acc[2 * q + 1][1], xq.y, wq.y);
            }
        }
    }

#pragma unroll
    for (int r = 0; r < 8; r++) {
        int n = n0 + ty * 8 + r;
        float4 v;
        unpack2(acc[r][0], v.x, v.y);
        unpack2(acc[r][1], v.z, v.w);
        *(float4*)&g_Z[(size_t)n * H_ + jj] = v;
    }
}

// ---------------------------------------------------------------------------
// Recurrence v5b: identical protocol to round 11 PLUS the trailing cluster
// rendezvous. Without it, a fast CTA exits while a slow peer's final remote
// mbarrier arrive is in flight -> DSMEM access to retired CTA -> ULF.
// ---------------------------------------------------------------------------
__global__ void __cluster_dims__(4, 1, 1) __launch_bounds__(256, 1)
mgu_recur5(int layer, float* __restrict__ Yext, float* __restrict__ Hfin)
{
    __shared__ __align__(16) u64 hbuf[2][2][256];   // [parity][batch][k] splatted {h,h}
    __shared__ __align__(16) u64 red[2][4][65];     // [batch][kq][col] partial sums
    __shared__ __align__(8)  u64 mbars[2];          // per-parity mbarrier, count=4

    const int tid = threadIdx.x;
    const int jl  = tid & 63;              // local column
    const int kq  = tid >> 6;              // K-quarter 0..3
    const uint32_t rank = cluster_rank();  // 0..3 -> column block
    const int c   = blockIdx.x >> 2;       // cluster id -> batch pair
    const int b0  = 2 * c;
    const int jg  = (int)rank * 64 + jl;   // global column

    const u64* __restrict__ Whg = g_Wh[layer];
    float* __restrict__ Y = (layer == 0) ? (float*)g_y1 : Yext;

    // This thread's 32 weight k-pairs -> registers (step-invariant).
    u64 wreg[64];
#pragma unroll
    for (int i = 0; i < 32; i++) {
        int k = 2 * (kq * 32 + i);
        wreg[2 * i]     = Whg[(size_t)k * H_ + jg];
        wreg[2 * i + 1] = Whg[(size_t)(k + 1) * H_ + jg];
    }

    // init: zero parity-0 h buffers; init both mbarriers (4 arrivals each)
    for (int m = tid; m < 512; m += 256) (&hbuf[0][0][0])[m] = 0ULL;
    if (tid == 0) {
        mbar_init(smem_u32(&mbars[0]), 4);
        mbar_init(smem_u32(&mbars[1]), 4);
    }
    __syncthreads();
    cluster_arrive();   // cluster-wide: init visible before any peer arrives/stores
    cluster_wait();

    const uint32_t hb_addr = smem_u32(&hbuf[0][0][0]);
    uint32_t peer[4], peerM[2][4];
#pragma unroll
    for (int r = 0; r < 4; r++) {
        peer[r]     = mapa_u32(hb_addr, (uint32_t)r);
        peerM[0][r] = mapa_u32(smem_u32(&mbars[0]), (uint32_t)r);
        peerM[1][r] = mapa_u32(smem_u32(&mbars[1]), (uint32_t)r);
    }
    const uint32_t myM0 = smem_u32(&mbars[0]);
    const uint32_t myM1 = smem_u32(&mbars[1]);

    // Epilogue task mapping: tid < 128 -> (batch bsel, column tcol)
    const int  bsel   = tid >> 6;                        // 0/1 (valid for tid<128)
    const int  tcol   = jl;                              // 0..63
    const int  tjg    = (int)rank * 64 + tcol;
    const bool isTask = (tid < 128);
    const size_t zbT  = (size_t)(b0 + bsel) * T_ * H_ + tjg;

    float2 zt = make_float2(0.f, 0.f);
    if (isTask) zt = g_Z[zbT];             // prefetch z for t=0

    int phv0 = 0, phv1 = 0;                // phase trackers for mbar[0], mbar[1]

    for (int t = 0; t < T_; t++) {
        const int p = t & 1, q = p ^ 1;

        // Wait for parity-p h (written by all 4 CTAs during step t-1).
        if (t > 0) {
            if (p == 0) { mbar_wait_cluster(myM0, phv0); phv0 ^= 1; }
            else        { mbar_wait_cluster(myM1, phv1); phv1 ^= 1; }
        }

        const u64* __restrict__ hbp0 = &hbuf[p][0][0];
        const u64* __restrict__ hbp1 = &hbuf[p][1][0];

        u64 a0e = 0, a0o = 0, a1e = 0, a1o = 0;
#pragma unroll
        for (int i = 0; i < 32; i++) {
            int kp = kq * 32 + i;
            ulonglong2 ha = *(const ulonglong2*)(hbp0 + 2 * kp);  // broadcast
            ulonglong2 hb = *(const ulonglong2*)(hbp1 + 2 * kp);  // broadcast
            ffma2(a0e, ha.x, wreg[2 * i]);
            ffma2(a0o, ha.y, wreg[2 * i + 1]);
            ffma2(a1e, hb.x, wreg[2 * i]);
            ffma2(a1o, hb.y, wreg[2 * i + 1]);
        }
        red[0][kq][jl] = fadd2(a0e, a0o);
        red[1][kq][jl] = fadd2(a1e, a1o);
        __syncthreads();

        float hn = 0.f;
        if (isTask) {
            u64 s = fadd2(fadd2(red[bsel][0][tcol], red[bsel][1][tcol]),
                          fadd2(red[bsel][2][tcol], red[bsel][3][tcol]));
            float af, ac;
            unpack2(s, af, ac);
            af += zt.x;
            ac += zt.y;

            float hold, dm;
            unpack2((bsel ? hbp1 : hbp0)[tjg], hold, dm);
            (void)dm;

            float f  = fmaf(0.5f, tanh_fast(0.5f * af), 0.5f);   // sigmoid
            float cg = tanh_fast(ac);
            hn = fmaf(f, hold - cg, cg);                         // f*h + (1-f)*c

            u64 pk = pack2(hn, hn);
            uint32_t off = (uint32_t)(((q * 2 + bsel) * 256 + tjg) * 8);
#pragma unroll
            for (int r = 0; r < 4; r++)
                st_cluster_u64(peer[r] + off, pk);   // includes self
        }
        __syncthreads();        // all task stores issued (intra-CTA HB to arrivers)

        if (tid < 4) {
            fence_cluster();    // publish this CTA's DSMEM stores cluster-wide
            mbar_arrive_cluster(peerM[q][tid]);   // 1 arrival per source CTA
        }

        // overlap arrive latency with global traffic
        if (isTask) {
            Y[zbT + (size_t)t * H_] = hn;
            if (t == T_ - 1) {
                Hfin[(b0 + bsel) * H_ + tjg] = hn;
            } else {
                zt = g_Z[zbT + (size_t)(t + 1) * H_];
            }
        }
    }

    // FIX (round-11 ULF): full-cluster rendezvous before exit. Guarantees all
    // CTAs are still resident when the final remote mbarrier arrives land.
    cluster_arrive();
    cluster_wait();
}

// ---------------------------------------------------------------------------
// Launch
// ---------------------------------------------------------------------------
extern "C" void kernel_launch(void* const* d_in, const int* in_sizes, int n_in,
                              void* d_out, int out_size)
{
    const float* x   = (const float*)d_in[0];
    const float* Wf1 = (const float*)d_in[1];
    const float* bf1 = (const float*)d_in[2];
    const float* Wc1 = (const float*)d_in[3];
    const float* bc1 = (const float*)d_in[4];
    const float* Wf2 = (const float*)d_in[5];
    const float* bf2 = (const float*)d_in[6];
    const float* Wc2 = (const float*)d_in[7];
    const float* bc2 = (const float*)d_in[8];

    float* out = (float*)d_out;
    float* y2  = out;                               // [B, T, H]
    float* h1  = out + (size_t)NT * H_;             // hidden[0]
    float* h2  = h1 + (size_t)B_ * H_;              // hidden[1]

    // weight repack (both layers)
    repack_wh<<<H_, H_>>>(Wf1, Wc1, I_, 0);
    repack_wh<<<H_, H_>>>(Wf2, Wc2, H_, 1);

    // layer 1
    gemm_x<<<dim3(NT / 128, H_ / 32), 256>>>(x, I_, 0, Wf1, Wc1, bf1, bc1);
    mgu_recur5<<<128, 256>>>(0, nullptr, h1);

    // layer 2 (reads g_y1)
    gemm_x<<<dim3(NT / 128, H_ / 32), 256>>>(nullptr, H_, 1, Wf2, Wc2, bf2, bc2);
    mgu_recur5<<<128, 256>>>(1, y2, h2);
}

// round 14
// speedup vs baseline: 1.7925x; 1.3022x over previous
#include <cuda_runtime.h>
#include <cuda_bf16.h>
#include <cstdint>
#include <math.h>

// Problem constants
#define B_  64
#define T_  1024
#define I_  128
#define H_  256
#define NT  (B_ * T_)          // 65536 rows

typedef unsigned long long u64;

// ---------------------------------------------------------------------------
// Static device scratch (no runtime allocation allowed)
// ---------------------------------------------------------------------------
__device__ float2 g_Z[(size_t)NT * H_];        // {zf, zc} x-part (+bias), 128 MB
__device__ float  g_y1[(size_t)NT * H_];       // layer-1 outputs, 64 MB
__device__ u64    g_Wh[2][H_ * H_];            // recurrent weights {wf,wc} packed, k-major

// ---------------------------------------------------------------------------
// f32x2 + PTX helpers
// ---------------------------------------------------------------------------
__device__ __forceinline__ u64 pack2(float x, float y) {
    u64 r;
    asm("mov.b64 %0, {%1, %2};" : "=l"(r) : "f"(x), "f"(y));
    return r;
}
__device__ __forceinline__ void unpack2(u64 v, float& x, float& y) {
    asm("mov.b64 {%0, %1}, %2;" : "=f"(x), "=f"(y) : "l"(v));
}
__device__ __forceinline__ void ffma2(u64& d, u64 a, u64 b) {
    asm("fma.rn.f32x2 %0, %1, %2, %0;" : "+l"(d) : "l"(a), "l"(b));
}
__device__ __forceinline__ u64 fadd2(u64 a, u64 b) {
    u64 d;
    asm("add.rn.f32x2 %0, %1, %2;" : "=l"(d) : "l"(a), "l"(b));
    return d;
}
__device__ __forceinline__ float tanh_fast(float x) {   // MUFU.TANH
    float y;
    asm("tanh.approx.f32 %0, %1;" : "=f"(y) : "f"(x));
    return y;
}
__device__ __forceinline__ uint32_t smem_u32(const void* p) {
    uint32_t a;
    asm("{ .reg .u64 t; cvta.to.shared.u64 t, %1; cvt.u32.u64 %0, t; }"
        : "=r"(a) : "l"(p));
    return a;
}
__device__ __forceinline__ uint32_t cluster_rank() {
    uint32_t r;
    asm("mov.u32 %0, %%cluster_ctarank;" : "=r"(r));
    return r;
}
__device__ __forceinline__ uint32_t mapa_u32(uint32_t addr, uint32_t rank) {
    uint32_t r;
    asm("mapa.shared::cluster.u32 %0, %1, %2;" : "=r"(r) : "r"(addr), "r"(rank));
    return r;
}
__device__ __forceinline__ void cluster_arrive() {
    asm volatile("barrier.cluster.arrive.aligned;" ::: "memory");
}
__device__ __forceinline__ void cluster_wait() {
    asm volatile("barrier.cluster.wait.aligned;" ::: "memory");
}
__device__ __forceinline__ void mbar_init(uint32_t addr, uint32_t count) {
    asm volatile("mbarrier.init.shared.b64 [%0], %1;" :: "r"(addr), "r"(count) : "memory");
}
// Combined: +1 arrival and +bytes expected tx on the CURRENT phase (local barrier).
__device__ __forceinline__ void mbar_arrive_expect_tx(uint32_t addr, uint32_t bytes) {
    asm volatile("mbarrier.arrive.expect_tx.shared.b64 _, [%0], %1;"
                 :: "r"(addr), "r"(bytes) : "memory");
}
// Async remote store: value lands in peer SMEM, then peer's mbarrier tx-count
// is updated by the HW on completion. No fence needed — ordering per store.
__device__ __forceinline__ void st_async_u64(uint32_t raddr, u64 v, uint32_t rmbar) {
    asm volatile("st.async.shared::cluster.mbarrier::complete_tx::bytes.u64 [%0], %1, [%2];"
                 :: "r"(raddr), "l"(v), "r"(rmbar) : "memory");
}
// Spin-wait on local mbarrier phase, cluster-scope acquire.
__device__ __forceinline__ void mbar_wait_cluster(uint32_t addr, uint32_t parity) {
    uint32_t done;
    asm volatile(
        "{\n\t"
        ".reg .pred p;\n\t"
        "mbarrier.try_wait.parity.acquire.cluster.shared::cta.b64 p, [%1], %2;\n\t"
        "selp.b32 %0, 1, 0, p;\n\t"
        "}"
        : "=r"(done) : "r"(addr), "r"(parity) : "memory");
    if (!done) {
        asm volatile(
            "{\n\t"
            ".reg .pred P1;\n\t"
            "WAIT_LOOP_%=:\n\t"
            "mbarrier.try_wait.parity.acquire.cluster.shared::cta.b64 P1, [%0], %1, 0x989680;\n\t"
            "@P1 bra.uni WAIT_DONE_%=;\n\t"
            "bra.uni WAIT_LOOP_%=;\n\t"
            "WAIT_DONE_%=:\n\t"
            "}"
            :: "r"(addr), "r"(parity) : "memory");
    }
}
__device__ __forceinline__ void bar_arrive(int name, int count) {
    asm volatile("bar.arrive %0, %1;" :: "r"(name), "r"(count) : "memory");
}
__device__ __forceinline__ void bar_sync(int name, int count) {
    asm volatile("bar.sync %0, %1;" :: "r"(name), "r"(count) : "memory");
}

// ---------------------------------------------------------------------------
// Repack recurrent weight rows: g_Wh[layer][k*H + j] = pack{Wf[D+k][j], Wc[D+k][j]}
// ---------------------------------------------------------------------------
__global__ void repack_wh(const float* __restrict__ Wf, const float* __restrict__ Wc,
                          int D, int layer)
{
    int j = threadIdx.x;
    int k = blockIdx.x;
    float wf = Wf[(size_t)(D + k) * H_ + j];
    float wc = Wc[(size_t)(D + k) * H_ + j];
    g_Wh[layer][k * H_ + j] = pack2(wf, wc);
}

// ---------------------------------------------------------------------------
// Precompute x-part of both gates (unchanged, passing since round 6):
//   g_Z[n][j] = { bf[j] + sum_d X[n][d]*Wf[d][j],  bc[j] + sum_d X[n][d]*Wc[d][j] }
// ---------------------------------------------------------------------------
__global__ void __launch_bounds__(256) gemm_x(
    const float* __restrict__ Xext, int D, int useY1,
    const float* __restrict__ Wf, const float* __restrict__ Wc,
    const float* __restrict__ bf, const float* __restrict__ bc)
{
    const float* __restrict__ X = useY1 ? (const float*)g_y1 : Xext;

    __shared__ float2 Xs[16][130];   // x splatted {x,x}
    __shared__ float2 Ws[16][34];    // {wf,wc}

    const int tid = threadIdx.x;
    const int tx  = tid & 15;
    const int ty  = tid >> 4;
    const int n0  = blockIdx.x * 128;
    const int j0  = blockIdx.y * 32;
    const int jj  = j0 + 2 * tx;

    u64 acc[8][2];
    {
        u64 bi0 = pack2(bf[jj],     bc[jj]);
        u64 bi1 = pack2(bf[jj + 1], bc[jj + 1]);
#pragma unroll
        for (int r = 0; r < 8; r++) { acc[r][0] = bi0; acc[r][1] = bi1; }
    }

    for (int d0 = 0; d0 < D; d0 += 16) {
        __syncthreads();
        {
            int r  = tid >> 2;
            int c4 = (tid & 3) * 4;
#pragma unroll
            for (int rr = 0; rr < 2; rr++) {
                int row = r + rr * 64;
                float4 v = *(const float4*)&X[(size_t)(n0 + row) * D + d0 + c4];
                Xs[c4 + 0][row] = make_float2(v.x, v.x);
                Xs[c4 + 1][row] = make_float2(v.y, v.y);
                Xs[c4 + 2][row] = make_float2(v.z, v.z);
                Xs[c4 + 3][row] = make_float2(v.w, v.w);
            }
        }
        for (int e = tid; e < 512; e += 256) {
            int k = e >> 5, jw = e & 31;
            Ws[k][jw] = make_float2(Wf[(size_t)(d0 + k) * H_ + j0 + jw],
                                    Wc[(size_t)(d0 + k) * H_ + j0 + jw]);
        }
        __syncthreads();

#pragma unroll
        for (int kk = 0; kk < 16; kk++) {
            ulonglong2 wq = *(const ulonglong2*)&Ws[kk][2 * tx];
            const ulonglong2* xp = (const ulonglong2*)&Xs[kk][ty * 8];
#pragma unroll
            for (int q = 0; q < 4; q++) {
                ulonglong2 xq = xp[q];
                ffma2(acc[2 * q + 0][0], xq.x, wq.x);
                ffma2(acc[2 * q + 0][1], xq.x, wq.y);
                ffma2(acc[2 * q + 1][0], xq.y, wq.x);
                ffma2(acc[2 * q + 1][1], xq.y, wq.y);
            }
        }
    }

#pragma unroll
    for (int r = 0; r < 8; r++) {
        int n = n0 + ty * 8 + r;
        float4 v;
        unpack2(acc[r][0], v.x, v.y);
        unpack2(acc[r][1], v.z, v.w);
        *(float4*)&g_Z[(size_t)n * H_ + jj] = v;
    }
}

// ---------------------------------------------------------------------------
// Recurrence v7: cluster of 4 CTAs, CTA = 64 cols x full K, 2 batches,
// 256 threads, register-resident weights.
// h exchange via st.async + tx-count mbarriers (HW-tracked completion):
//   - task thread stores its {h,h} to hbuf[q] in all 4 CTAs via st.async,
//     each store HW-updates the destination's mbars[q] tx-count on completion.
//   - each CTA's mbars[q] phase = 1 arrival (tid0 re-arm, +4096B expect) +
//     4096 bytes (4 CTAs x 128 threads x 8B).
//   - NO fence, NO second bar.sync: correctness by HW contract, not ordering.
// Asymmetric red barrier; h in task registers; stores skipped at t=T-1.
// ---------------------------------------------------------------------------
#define STEP_TX_BYTES 4096u

__global__ void __cluster_dims__(4, 1, 1) __launch_bounds__(256, 1)
mgu_recur7(int layer, float* __restrict__ Yext, float* __restrict__ Hfin)
{
    __shared__ __align__(16) u64 hbuf[2][2][256];   // [parity][batch][k] splatted {h,h}
    __shared__ __align__(16) u64 red[2][2][4][65];  // [parity][batch][kq][col]
    __shared__ __align__(8)  u64 mbars[2];          // per-parity tx mbarrier

    const int tid = threadIdx.x;
    const int jl  = tid & 63;              // local column
    const int kq  = tid >> 6;              // K-quarter 0..3
    const uint32_t rank = cluster_rank();  // 0..3 -> column block
    const int c   = blockIdx.x >> 2;       // cluster id -> batch pair
    const int b0  = 2 * c;
    const int jg  = (int)rank * 64 + jl;   // global column

    const u64* __restrict__ Whg = g_Wh[layer];
    float* __restrict__ Y = (layer == 0) ? (float*)g_y1 : Yext;

    // This thread's 32 weight k-pairs -> registers (step-invariant).
    u64 wreg[64];
#pragma unroll
    for (int i = 0; i < 32; i++) {
        int k = 2 * (kq * 32 + i);
        wreg[2 * i]     = Whg[(size_t)k * H_ + jg];
        wreg[2 * i + 1] = Whg[(size_t)(k + 1) * H_ + jg];
    }

    // init: zero parity-0 h buffers; init + arm both tx barriers (count=1)
    for (int m = tid; m < 512; m += 256) (&hbuf[0][0][0])[m] = 0ULL;
    if (tid == 0) {
        mbar_init(smem_u32(&mbars[0]), 1);
        mbar_init(smem_u32(&mbars[1]), 1);
        // arm phase 0 of both: 1 arrival + 4096B expected each
        mbar_arrive_expect_tx(smem_u32(&mbars[0]), STEP_TX_BYTES);
        mbar_arrive_expect_tx(smem_u32(&mbars[1]), STEP_TX_BYTES);
    }
    __syncthreads();
    cluster_arrive();   // cluster-wide: init/arm visible before any peer stores
    cluster_wait();

    const uint32_t hb_addr = smem_u32(&hbuf[0][0][0]);
    uint32_t peer[4], peerM[2][4];
#pragma unroll
    for (int r = 0; r < 4; r++) {
        peer[r]     = mapa_u32(hb_addr, (uint32_t)r);
        peerM[0][r] = mapa_u32(smem_u32(&mbars[0]), (uint32_t)r);
        peerM[1][r] = mapa_u32(smem_u32(&mbars[1]), (uint32_t)r);
    }
    const uint32_t myM[2] = { smem_u32(&mbars[0]), smem_u32(&mbars[1]) };

    // Task mapping: warps 0-3 (tid<128) -> (batch bsel, column tcol).
    const int  bsel   = (tid >> 6) & 1;                  // valid for tid<128
    const int  tcol   = jl;
    const int  tjg    = (int)rank * 64 + tcol;
    const bool isTask = (tid < 128);
    const size_t zbT  = (size_t)(b0 + bsel) * T_ * H_ + tjg;

    float2 zt = make_float2(0.f, 0.f);
    float  h_reg = 0.f;                    // this task thread's own h (register)
    if (isTask) zt = g_Z[zbT];             // prefetch z for t=0

    int phv[2] = { 0, 0 };                 // phase trackers for mbars[0/1]

    for (int t = 0; t < T_; t++) {
        const int p = t & 1, q = p ^ 1;

        // Wait for parity-p h (all 4096 bytes landed + re-arm arrival).
        if (t > 0) {
            mbar_wait_cluster(myM[p], phv[p]);
            phv[p] ^= 1;
            // re-arm the NEW phase of this barrier (used again at t+2)
            if (tid == 0) mbar_arrive_expect_tx(myM[p], STEP_TX_BYTES);
        }

        const u64* __restrict__ hbp0 = &hbuf[p][0][0];
        const u64* __restrict__ hbp1 = &hbuf[p][1][0];

        u64 a0e = 0, a0o = 0, a1e = 0, a1o = 0;
#pragma unroll
        for (int i = 0; i < 32; i++) {
            int kp = kq * 32 + i;
            ulonglong2 ha = *(const ulonglong2*)(hbp0 + 2 * kp);  // broadcast
            ulonglong2 hb = *(const ulonglong2*)(hbp1 + 2 * kp);  // broadcast
            ffma2(a0e, ha.x, wreg[2 * i]);
            ffma2(a0o, ha.y, wreg[2 * i + 1]);
            ffma2(a1e, hb.x, wreg[2 * i]);
            ffma2(a1o, hb.y, wreg[2 * i + 1]);
        }
        red[p][0][kq][jl] = fadd2(a0e, a0o);
        red[p][1][kq][jl] = fadd2(a1e, a1o);

        if (!isTask) {
            bar_arrive(1, 256);    // signal red written; straight to next wait
            continue;
        }
        bar_sync(1, 256);          // red[p] complete (all 8 warps)

        // ---- parallel epilogue: one (col,batch) per task thread ----
        u64 s = fadd2(fadd2(red[p][bsel][0][tcol], red[p][bsel][1][tcol]),
                      fadd2(red[p][bsel][2][tcol], red[p][bsel][3][tcol]));
        float af, ac;
        unpack2(s, af, ac);
        af += zt.x;
        ac += zt.y;

        float f  = fmaf(0.5f, tanh_fast(0.5f * af), 0.5f);   // sigmoid
        float cg = tanh_fast(ac);
        h_reg = fmaf(f, h_reg - cg, cg);                     // f*h + (1-f)*c

        if (t < T_ - 1) {
            // publish h for step t+1: 4 async stores, HW-tracked completion
            u64 pk = pack2(h_reg, h_reg);
            uint32_t off = (uint32_t)(((q * 2 + bsel) * 256 + tjg) * 8);
#pragma unroll
            for (int r = 0; r < 4; r++)
                st_async_u64(peer[r] + off, pk, peerM[q][r]);
            // overlap store flight with global traffic
            Y[zbT + (size_t)t * H_] = h_reg;
            zt = g_Z[zbT + (size_t)(t + 1) * H_];
        } else {
            Y[zbT + (size_t)t * H_] = h_reg;
            Hfin[(b0 + bsel) * H_ + tjg] = h_reg;
        }
    }

    // trailing rendezvous: keep all CTAs resident until everything drains
    cluster_arrive();
    cluster_wait();
}

// ---------------------------------------------------------------------------
// Launch
// ---------------------------------------------------------------------------
extern "C" void kernel_launch(void* const* d_in, const int* in_sizes, int n_in,
                              void* d_out, int out_size)
{
    const float* x   = (const float*)d_in[0];
    const float* Wf1 = (const float*)d_in[1];
    const float* bf1 = (const float*)d_in[2];
    const float* Wc1 = (const float*)d_in[3];
    const float* bc1 = (const float*)d_in[4];
    const float* Wf2 = (const float*)d_in[5];
    const float* bf2 = (const float*)d_in[6];
    const float* Wc2 = (const float*)d_in[7];
    const float* bc2 = (const float*)d_in[8];

    float* out = (float*)d_out;
    float* y2  = out;                               // [B, T, H]
    float* h1  = out + (size_t)NT * H_;             // hidden[0]
    float* h2  = h1 + (size_t)B_ * H_;              // hidden[1]

    // weight repack (both layers)
    repack_wh<<<H_, H_>>>(Wf1, Wc1, I_, 0);
    repack_wh<<<H_, H_>>>(Wf2, Wc2, H_, 1);

    // layer 1
    gemm_x<<<dim3(NT / 128, H_ / 32), 256>>>(x, I_, 0, Wf1, Wc1, bf1, bc1);
    mgu_recur7<<<128, 256>>>(0, nullptr, h1);

    // layer 2 (reads g_y1)
    gemm_x<<<dim3(NT / 128, H_ / 32), 256>>>(nullptr, H_, 1, Wf2, Wc2, bf2, bc2);
    mgu_recur7<<<128, 256>>>(1, y2, h2);
}